// round 11
// baseline (speedup 1.0000x reference)
#include <cuda_runtime.h>
#include <cuda_fp16.h>
#include <mma.h>
#include <cstdint>

using namespace nvcuda;

#define NN   50000
#define NPAD 50048                 // NN rounded to 128 (gemm stores full tiles)
#define DD   128
#define EMAX 1600000

// ---------------- device scratch ----------------
__device__ __align__(16) float g_dinv[NN];
__device__ int g_degi[NN];
__device__ int g_off[NN + 1];
__device__ int g_cur[NN];
__device__ int g_csr[EMAX];
__device__ __align__(16) float g_hs[(size_t)NPAD * DD];   // fp32 features
__device__ __align__(16) float g_x2[(size_t)NN * DD];
__device__ int g_is64;

#define ADD_F32X2(acc, v) \
    asm("add.rn.f32x2 %0, %0, %1;" : "+l"(acc) : "l"(v))

// ---------------- prep ------------------------------------------------------
__device__ __forceinline__ int detect_is64(const unsigned* ei) {
    unsigned hi = ei[(threadIdx.x & 31) * 2 + 1];
    unsigned any = __ballot_sync(0xFFFFFFFFu, hi != 0u);
    return (any == 0u) ? 1 : 0;
}

__global__ void k_count(const void* __restrict__ ei, int E) {
    __shared__ int s_is64;
    if (threadIdx.x < 32) {
        int is64 = detect_is64((const unsigned*)ei);
        if (threadIdx.x == 0) {
            s_is64 = is64;
            if (blockIdx.x == 0) g_is64 = is64;
        }
    }
    __syncthreads();
    int i = blockIdx.x * blockDim.x + threadIdx.x;
    if (i >= E) return;
    int d;
    if (s_is64) d = (int)((const long long*)ei)[(size_t)E + i];
    else        d = ((const int*)ei)[(size_t)E + i];
    atomicAdd(&g_degi[d], 1);
}

__global__ void __launch_bounds__(1024) k_scan(int N) {
    __shared__ int part[1024];
    const int t = threadIdx.x;
    const int C = (N + 1023) >> 10;
    const int lo = t * C;
    const int hi = min(lo + C, N);
    int s = 0;
    for (int i = lo; i < hi; ++i) s += g_degi[i];
    part[t] = s;
    __syncthreads();
    for (int o = 1; o < 1024; o <<= 1) {
        int v = (t >= o) ? part[t - o] : 0;
        __syncthreads();
        part[t] += v;
        __syncthreads();
    }
    int run = (t > 0) ? part[t - 1] : 0;
    for (int i = lo; i < hi; ++i) {
        int dg = g_degi[i];
        g_off[i] = run;
        g_cur[i] = run;
        g_dinv[i] = rsqrtf((float)(dg + 1));
        run += dg;
    }
    if (t == 0) g_off[N] = part[1023];
}

__global__ void k_fill(const void* __restrict__ ei, int E) {
    int i = blockIdx.x * blockDim.x + threadIdx.x;
    if (i >= E) return;
    int s, d;
    if (g_is64) {
        const long long* p = (const long long*)ei;
        s = (int)p[i];
        d = (int)p[(size_t)E + i];
    } else {
        const int* p = (const int*)ei;
        s = p[i];
        d = p[(size_t)E + i];
    }
    int pos = atomicAdd(&g_cur[d], 1);
    g_csr[pos] = s;
}

// ---------------- wmma GEMM: HS[fp32] = (X*dinv[row]) @ W -------------------
// dinv folded into A staging; C fragments stored DIRECTLY to global fp32.
#define LDA 136
#define SM_A_BYTES (128 * LDA * 2)          // 34816
#define SM_TOTAL   (2 * SM_A_BYTES)         // 69632

__global__ void __launch_bounds__(256) k_gemm(
    const float* __restrict__ X, const float* __restrict__ W,
    float* __restrict__ H, int N)
{
    extern __shared__ char sm[];
    __half* As = (__half*)sm;
    __half* Bs = (__half*)(sm + SM_A_BYTES);

    const int tx = threadIdx.x;
    const int row0 = blockIdx.x * 128;
    const int r  = tx >> 1;
    const int ch = (tx & 1) * 64;

    // ---- stage A = X * dinv[row] (fp16) and B = W (fp16) ----
    {
        const int grow = row0 + r;
        const float sc = (grow < N) ? g_dinv[grow] : 0.f;
        __half* ad = As + r * LDA + ch;
        const float4* xs = (const float4*)(X + (size_t)grow * 128 + ch);
#pragma unroll
        for (int i = 0; i < 16; ++i) {
            float4 v = (grow < N) ? __ldg(xs + i) : make_float4(0.f, 0.f, 0.f, 0.f);
            __half2 h0 = __floats2half2_rn(v.x * sc, v.y * sc);
            __half2 h1 = __floats2half2_rn(v.z * sc, v.w * sc);
            *(uint2*)(ad + i * 4) = make_uint2(*(unsigned*)&h0, *(unsigned*)&h1);
        }
        __half* bd = Bs + r * LDA + ch;
        const float4* ws = (const float4*)(W + (size_t)r * 128 + ch);
#pragma unroll
        for (int i = 0; i < 16; ++i) {
            float4 v = __ldg(ws + i);
            __half2 h0 = __floats2half2_rn(v.x, v.y);
            __half2 h1 = __floats2half2_rn(v.z, v.w);
            *(uint2*)(bd + i * 4) = make_uint2(*(unsigned*)&h0, *(unsigned*)&h1);
        }
    }
    __syncthreads();

    // ---- wmma mainloop ----
    const int wid = tx >> 5;
    const int wm = wid & 3;        // rows wm*32 .. +31
    const int wn = wid >> 2;       // cols wn*64 .. +63

    wmma::fragment<wmma::accumulator, 16, 16, 16, float> c[2][4];
#pragma unroll
    for (int i = 0; i < 2; ++i)
#pragma unroll
        for (int j = 0; j < 4; ++j) wmma::fill_fragment(c[i][j], 0.f);

#pragma unroll
    for (int kk = 0; kk < 8; ++kk) {
        wmma::fragment<wmma::matrix_a, 16, 16, 16, __half, wmma::row_major> a[2];
        wmma::load_matrix_sync(a[0], As + (wm * 32 + 0)  * LDA + kk * 16, LDA);
        wmma::load_matrix_sync(a[1], As + (wm * 32 + 16) * LDA + kk * 16, LDA);
#pragma unroll
        for (int j = 0; j < 4; ++j) {
            wmma::fragment<wmma::matrix_b, 16, 16, 16, __half, wmma::row_major> b;
            wmma::load_matrix_sync(b, Bs + (kk * 16) * LDA + wn * 64 + j * 16, LDA);
            wmma::mma_sync(c[0][j], a[0], b, c[0][j]);
            wmma::mma_sync(c[1][j], a[1], b, c[1][j]);
        }
    }

    // ---- store fragments directly to global fp32 (H padded to NPAD rows) ----
#pragma unroll
    for (int i = 0; i < 2; ++i)
#pragma unroll
        for (int j = 0; j < 4; ++j)
            wmma::store_matrix_sync(
                H + (size_t)(row0 + wm * 32 + i * 16) * 128 + wn * 64 + j * 16,
                c[i][j], 128, wmma::mem_row_major);
}

// --------- fused pull-aggregation (fp32, packed f32x2) + bias + LN + ELU ---
// Warp per node, FULL warp per edge: lane owns 16B (4 floats = 2 f32x2).
__global__ void __launch_bounds__(256, 4) k_aggln(
    const float* __restrict__ hs, const float* __restrict__ bias,
    const float* __restrict__ gma, const float* __restrict__ bet,
    float* __restrict__ out, int N)
{
    int gt = blockIdx.x * blockDim.x + threadIdx.x;
    int row = gt >> 5;
    int lane = gt & 31;
    if (row >= N) return;

    const ulonglong2* hv = (const ulonglong2*)hs;   // 32 x 16B per row

    // self-loop term
    unsigned long long a0, a1;
    {
        ulonglong2 v = __ldg(&hv[(size_t)row * 32 + lane]);
        a0 = v.x; a1 = v.y;
    }

    int e = g_off[row];
    const int end = g_off[row + 1];

    // 8-edge batches: 8 independent LDG.128 in flight
    while (e + 8 <= end) {
        int i0 = g_csr[e + 0], i1 = g_csr[e + 1], i2 = g_csr[e + 2], i3 = g_csr[e + 3];
        int i4 = g_csr[e + 4], i5 = g_csr[e + 5], i6 = g_csr[e + 6], i7 = g_csr[e + 7];
        ulonglong2 v0 = __ldg(&hv[(size_t)i0 * 32 + lane]);
        ulonglong2 v1 = __ldg(&hv[(size_t)i1 * 32 + lane]);
        ulonglong2 v2 = __ldg(&hv[(size_t)i2 * 32 + lane]);
        ulonglong2 v3 = __ldg(&hv[(size_t)i3 * 32 + lane]);
        ulonglong2 v4 = __ldg(&hv[(size_t)i4 * 32 + lane]);
        ulonglong2 v5 = __ldg(&hv[(size_t)i5 * 32 + lane]);
        ulonglong2 v6 = __ldg(&hv[(size_t)i6 * 32 + lane]);
        ulonglong2 v7 = __ldg(&hv[(size_t)i7 * 32 + lane]);
        ADD_F32X2(a0, v0.x); ADD_F32X2(a1, v0.y);
        ADD_F32X2(a0, v1.x); ADD_F32X2(a1, v1.y);
        ADD_F32X2(a0, v2.x); ADD_F32X2(a1, v2.y);
        ADD_F32X2(a0, v3.x); ADD_F32X2(a1, v3.y);
        ADD_F32X2(a0, v4.x); ADD_F32X2(a1, v4.y);
        ADD_F32X2(a0, v5.x); ADD_F32X2(a1, v5.y);
        ADD_F32X2(a0, v6.x); ADD_F32X2(a1, v6.y);
        ADD_F32X2(a0, v7.x); ADD_F32X2(a1, v7.y);
        e += 8;
    }
    while (e < end) {
        int i0 = g_csr[e];
        ulonglong2 v0 = __ldg(&hv[(size_t)i0 * 32 + lane]);
        ADD_F32X2(a0, v0.x); ADD_F32X2(a1, v0.y);
        ++e;
    }

    // unpack accumulators
    float acc[4];
    {
        unsigned lo, hi;
        asm("mov.b64 {%0,%1}, %2;" : "=r"(lo), "=r"(hi) : "l"(a0));
        acc[0] = __uint_as_float(lo); acc[1] = __uint_as_float(hi);
        asm("mov.b64 {%0,%1}, %2;" : "=r"(lo), "=r"(hi) : "l"(a1));
        acc[2] = __uint_as_float(lo); acc[3] = __uint_as_float(hi);
    }

    // t = acc * dinv[row] + bias   (src-side dinv already folded into hs)
    float sc = g_dinv[row];
    float4 b = ((const float4*)bias)[lane];
    float t[4];
    t[0] = fmaf(acc[0], sc, b.x);
    t[1] = fmaf(acc[1], sc, b.y);
    t[2] = fmaf(acc[2], sc, b.z);
    t[3] = fmaf(acc[3], sc, b.w);

    float s = t[0] + t[1] + t[2] + t[3];
    float sq = t[0]*t[0] + t[1]*t[1] + t[2]*t[2] + t[3]*t[3];
#pragma unroll
    for (int o = 16; o; o >>= 1) {
        s  += __shfl_xor_sync(0xFFFFFFFFu, s,  o);
        sq += __shfl_xor_sync(0xFFFFFFFFu, sq, o);
    }
    float mean = s * (1.0f / 128.0f);
    float var  = sq * (1.0f / 128.0f) - mean * mean;
    float rstd = rsqrtf(var + 1e-5f);

    float4 g = ((const float4*)gma)[lane];
    float4 be = ((const float4*)bet)[lane];
    float4 o;
    float u;
    u = (t[0] - mean) * rstd * g.x + be.x; o.x = u > 0.f ? u : expm1f(u);
    u = (t[1] - mean) * rstd * g.y + be.y; o.y = u > 0.f ? u : expm1f(u);
    u = (t[2] - mean) * rstd * g.z + be.z; o.z = u > 0.f ? u : expm1f(u);
    u = (t[3] - mean) * rstd * g.w + be.w; o.w = u > 0.f ? u : expm1f(u);

    ((float4*)(out + (size_t)row * 128))[lane] = o;
}

// ---------------- launch ----------------------------------------------------
extern "C" void kernel_launch(void* const* d_in, const int* in_sizes, int n_in,
                              void* d_out, int out_size)
{
    const float* x   = (const float*)d_in[0];
    const void*  ei  = d_in[1];
    const float* W1  = (const float*)d_in[2];
    const float* b1  = (const float*)d_in[3];
    const float* g1  = (const float*)d_in[4];
    const float* be1 = (const float*)d_in[5];
    const float* W2  = (const float*)d_in[6];
    const float* b2  = (const float*)d_in[7];
    const float* g2  = (const float*)d_in[8];
    const float* be2 = (const float*)d_in[9];

    int N = in_sizes[0] / DD;  if (N > NN)   N = NN;
    int E = in_sizes[1] / 2;   if (E > EMAX) E = EMAX;
    float* out = (float*)d_out;

    float *hs, *x2;
    void* degi;
    cudaGetSymbolAddress((void**)&hs,  g_hs);
    cudaGetSymbolAddress((void**)&x2,  g_x2);
    cudaGetSymbolAddress(&degi, g_degi);

    const int T = 256;
    cudaFuncSetAttribute(k_gemm, cudaFuncAttributeMaxDynamicSharedMemorySize, SM_TOTAL);

    int ebl = (E + T - 1) / T;
    int abl = (N + 7) / 8;
    int gbl = (N + 127) / 128;

    // ---- graph preprocessing ----
    cudaMemsetAsync(degi, 0, (size_t)N * sizeof(int));
    k_count<<<ebl, T>>>(ei, E);
    k_scan<<<1, 1024>>>(N);
    k_fill<<<ebl, T>>>(ei, E);

    // ---- layer 1 ----
    k_gemm<<<gbl, T, SM_TOTAL>>>(x, W1, hs, N);
    k_aggln<<<abl, T>>>(hs, b1, g1, be1, x2, N);

    // ---- layer 2 ----
    k_gemm<<<gbl, T, SM_TOTAL>>>(x2, W2, hs, N);
    k_aggln<<<abl, T>>>(hs, b2, g2, be2, out, N);
}

// round 12
// speedup vs baseline: 1.0637x; 1.0637x over previous
#include <cuda_runtime.h>
#include <cuda_fp16.h>
#include <mma.h>
#include <cstdint>

using namespace nvcuda;

#define NN   50000
#define DD   128
#define EMAX 1600000

// ---------------- device scratch ----------------
__device__ __align__(16) float g_dinv[NN];
__device__ int g_degi[NN];
__device__ int g_off[NN + 1];
__device__ int g_cur[NN];
__device__ int g_csr[EMAX];
__device__ __align__(16) __half g_hs[(size_t)NN * DD];
__device__ __align__(16) float g_x2[(size_t)NN * DD];
__device__ int g_is64;

// ---------------- prep ------------------------------------------------------
__device__ __forceinline__ int detect_is64(const unsigned* ei) {
    unsigned hi = ei[(threadIdx.x & 31) * 2 + 1];
    unsigned any = __ballot_sync(0xFFFFFFFFu, hi != 0u);
    return (any == 0u) ? 1 : 0;
}

__global__ void k_count(const void* __restrict__ ei, int E) {
    __shared__ int s_is64;
    if (threadIdx.x < 32) {
        int is64 = detect_is64((const unsigned*)ei);
        if (threadIdx.x == 0) {
            s_is64 = is64;
            if (blockIdx.x == 0) g_is64 = is64;
        }
    }
    __syncthreads();
    int i = blockIdx.x * blockDim.x + threadIdx.x;
    if (i >= E) return;
    int d;
    if (s_is64) d = (int)((const long long*)ei)[(size_t)E + i];
    else        d = ((const int*)ei)[(size_t)E + i];
    atomicAdd(&g_degi[d], 1);
}

__global__ void __launch_bounds__(1024) k_scan(int N) {
    __shared__ int part[1024];
    const int t = threadIdx.x;
    const int C = (N + 1023) >> 10;
    const int lo = t * C;
    const int hi = min(lo + C, N);
    int s = 0;
    for (int i = lo; i < hi; ++i) s += g_degi[i];
    part[t] = s;
    __syncthreads();
    for (int o = 1; o < 1024; o <<= 1) {
        int v = (t >= o) ? part[t - o] : 0;
        __syncthreads();
        part[t] += v;
        __syncthreads();
    }
    int run = (t > 0) ? part[t - 1] : 0;
    for (int i = lo; i < hi; ++i) {
        int dg = g_degi[i];
        g_off[i] = run;
        g_cur[i] = run;
        g_dinv[i] = rsqrtf((float)(dg + 1));
        run += dg;
    }
    if (t == 0) g_off[N] = part[1023];
}

__global__ void k_fill(const void* __restrict__ ei, int E) {
    int i = blockIdx.x * blockDim.x + threadIdx.x;
    if (i >= E) return;
    int s, d;
    if (g_is64) {
        const long long* p = (const long long*)ei;
        s = (int)p[i];
        d = (int)p[(size_t)E + i];
    } else {
        const int* p = (const int*)ei;
        s = p[i];
        d = p[(size_t)E + i];
    }
    int pos = atomicAdd(&g_cur[d], 1);
    g_csr[pos] = s;
}

// ---------------- wmma GEMM: HS = fp16((X @ W) * dinv[row]) ----------------
// R10 version (measured 33.7us, best total 299.7).
#define LDA 136
#define LDC 132
#define SM_A_BYTES (128 * LDA * 2)
#define SM_TOTAL   (2 * SM_A_BYTES)

__global__ void __launch_bounds__(256) k_gemm(
    const float* __restrict__ X, const float* __restrict__ W,
    __half* __restrict__ H, int N)
{
    extern __shared__ char sm[];
    __half* As = (__half*)sm;
    __half* Bs = (__half*)(sm + SM_A_BYTES);
    float*  Cs = (float*)sm;

    const int tx = threadIdx.x;
    const int row0 = blockIdx.x * 128;
    const int r  = tx >> 1;
    const int ch = (tx & 1) * 64;

    {
        const int grow = row0 + r;
        __half* ad = As + r * LDA + ch;
        const float4* xs = (const float4*)(X + (size_t)grow * 128 + ch);
#pragma unroll
        for (int i = 0; i < 16; ++i) {
            float4 v = (grow < N) ? __ldg(xs + i) : make_float4(0.f, 0.f, 0.f, 0.f);
            __half2 h0 = __floats2half2_rn(v.x, v.y);
            __half2 h1 = __floats2half2_rn(v.z, v.w);
            *(uint2*)(ad + i * 4) = make_uint2(*(unsigned*)&h0, *(unsigned*)&h1);
        }
        __half* bd = Bs + r * LDA + ch;
        const float4* ws = (const float4*)(W + (size_t)r * 128 + ch);
#pragma unroll
        for (int i = 0; i < 16; ++i) {
            float4 v = __ldg(ws + i);
            __half2 h0 = __floats2half2_rn(v.x, v.y);
            __half2 h1 = __floats2half2_rn(v.z, v.w);
            *(uint2*)(bd + i * 4) = make_uint2(*(unsigned*)&h0, *(unsigned*)&h1);
        }
    }
    __syncthreads();

    const int wid = tx >> 5;
    const int wm = wid & 3;
    const int wn = wid >> 2;

    wmma::fragment<wmma::accumulator, 16, 16, 16, float> c[2][4];
#pragma unroll
    for (int i = 0; i < 2; ++i)
#pragma unroll
        for (int j = 0; j < 4; ++j) wmma::fill_fragment(c[i][j], 0.f);

#pragma unroll
    for (int kk = 0; kk < 8; ++kk) {
        wmma::fragment<wmma::matrix_a, 16, 16, 16, __half, wmma::row_major> a[2];
        wmma::load_matrix_sync(a[0], As + (wm * 32 + 0)  * LDA + kk * 16, LDA);
        wmma::load_matrix_sync(a[1], As + (wm * 32 + 16) * LDA + kk * 16, LDA);
#pragma unroll
        for (int j = 0; j < 4; ++j) {
            wmma::fragment<wmma::matrix_b, 16, 16, 16, __half, wmma::row_major> b;
            wmma::load_matrix_sync(b, Bs + (kk * 16) * LDA + wn * 64 + j * 16, LDA);
            wmma::mma_sync(c[0][j], a[0], b, c[0][j]);
            wmma::mma_sync(c[1][j], a[1], b, c[1][j]);
        }
    }
    __syncthreads();

#pragma unroll
    for (int i = 0; i < 2; ++i)
#pragma unroll
        for (int j = 0; j < 4; ++j)
            wmma::store_matrix_sync(Cs + (wm * 32 + i * 16) * LDC + wn * 64 + j * 16,
                                    c[i][j], LDC, wmma::mem_row_major);
    __syncthreads();

    {
        const int grow = row0 + r;
        if (grow < N) {
            float sc = g_dinv[grow];
            const float* src = Cs + r * LDC + ch;
            __half* dst = H + (size_t)grow * 128 + ch;
#pragma unroll
            for (int i = 0; i < 16; ++i) {
                float v0 = src[i * 4 + 0] * sc;
                float v1 = src[i * 4 + 1] * sc;
                float v2 = src[i * 4 + 2] * sc;
                float v3 = src[i * 4 + 3] * sc;
                __half2 h0 = __floats2half2_rn(v0, v1);
                __half2 h1 = __floats2half2_rn(v2, v3);
                *(uint2*)(dst + i * 4) = make_uint2(*(unsigned*)&h0, *(unsigned*)&h1);
            }
        }
    }
}

// --------- fused pull-aggregation + bias + LN + ELU (R10/R4 version) -------
__device__ __forceinline__ void add8(uint4 p, float* a) {
    float2 f;
    f = __half22float2(*(__half2*)&p.x); a[0] += f.x; a[1] += f.y;
    f = __half22float2(*(__half2*)&p.y); a[2] += f.x; a[3] += f.y;
    f = __half22float2(*(__half2*)&p.z); a[4] += f.x; a[5] += f.y;
    f = __half22float2(*(__half2*)&p.w); a[6] += f.x; a[7] += f.y;
}

__global__ void __launch_bounds__(256, 4) k_aggln(
    const __half* __restrict__ hs, const float* __restrict__ bias,
    const float* __restrict__ gma, const float* __restrict__ bet,
    float* __restrict__ out, int N)
{
    int gt = blockIdx.x * blockDim.x + threadIdx.x;
    int row = gt >> 5;
    int lane = gt & 31;
    if (row >= N) return;
    const int lh = lane >> 4;
    const int lc = lane & 15;

    const uint4* hv = (const uint4*)hs;

    float acc[8];
#pragma unroll
    for (int c = 0; c < 8; ++c) acc[c] = 0.f;
    if (lh == 0) {
        uint4 p = __ldg(&hv[(size_t)row * 16 + lc]);
        add8(p, acc);
    }

    int e = g_off[row];
    const int end = g_off[row + 1];

    while (e + 8 <= end) {
        int i0 = g_csr[e + 0 + lh];
        int i1 = g_csr[e + 2 + lh];
        int i2 = g_csr[e + 4 + lh];
        int i3 = g_csr[e + 6 + lh];
        uint4 p0 = __ldg(&hv[(size_t)i0 * 16 + lc]);
        uint4 p1 = __ldg(&hv[(size_t)i1 * 16 + lc]);
        uint4 p2 = __ldg(&hv[(size_t)i2 * 16 + lc]);
        uint4 p3 = __ldg(&hv[(size_t)i3 * 16 + lc]);
        add8(p0, acc);
        add8(p1, acc);
        add8(p2, acc);
        add8(p3, acc);
        e += 8;
    }
    while (e + 2 <= end) {
        int i0 = g_csr[e + lh];
        uint4 p0 = __ldg(&hv[(size_t)i0 * 16 + lc]);
        add8(p0, acc);
        e += 2;
    }
    if (e < end && lh == 0) {
        int i0 = g_csr[e];
        uint4 p0 = __ldg(&hv[(size_t)i0 * 16 + lc]);
        add8(p0, acc);
    }

#pragma unroll
    for (int c = 0; c < 8; ++c)
        acc[c] += __shfl_xor_sync(0xFFFFFFFFu, acc[c], 16);

    float sc = g_dinv[row];
    float4 b0 = ((const float4*)bias)[lc * 2];
    float4 b1 = ((const float4*)bias)[lc * 2 + 1];
    float t[8];
    t[0] = fmaf(acc[0], sc, b0.x); t[1] = fmaf(acc[1], sc, b0.y);
    t[2] = fmaf(acc[2], sc, b0.z); t[3] = fmaf(acc[3], sc, b0.w);
    t[4] = fmaf(acc[4], sc, b1.x); t[5] = fmaf(acc[5], sc, b1.y);
    t[6] = fmaf(acc[6], sc, b1.z); t[7] = fmaf(acc[7], sc, b1.w);

    float s = 0.f, sq = 0.f;
#pragma unroll
    for (int c = 0; c < 8; ++c) { s += t[c]; sq += t[c] * t[c]; }
#pragma unroll
    for (int o = 8; o; o >>= 1) {
        s  += __shfl_xor_sync(0xFFFFFFFFu, s,  o);
        sq += __shfl_xor_sync(0xFFFFFFFFu, sq, o);
    }
    float mean = s * (1.0f / 128.0f);
    float var  = sq * (1.0f / 128.0f) - mean * mean;
    float rstd = rsqrtf(var + 1e-5f);

    float4 g0 = ((const float4*)gma)[lc * 2];
    float4 g1 = ((const float4*)gma)[lc * 2 + 1];
    float4 e0 = ((const float4*)bet)[lc * 2];
    float4 e1 = ((const float4*)bet)[lc * 2 + 1];
    float gg[8] = {g0.x, g0.y, g0.z, g0.w, g1.x, g1.y, g1.z, g1.w};
    float bb[8] = {e0.x, e0.y, e0.z, e0.w, e1.x, e1.y, e1.z, e1.w};

    if (lh == 0) {
        float o[8];
#pragma unroll
        for (int c = 0; c < 8; ++c) {
            float u = (t[c] - mean) * rstd * gg[c] + bb[c];
            o[c] = u > 0.f ? u : expm1f(u);
        }
        float4* op = (float4*)(out + (size_t)row * 128 + lc * 8);
        op[0] = make_float4(o[0], o[1], o[2], o[3]);
        op[1] = make_float4(o[4], o[5], o[6], o[7]);
    }
}

// ---------------- launch: fork gemm1 parallel to fill -----------------------
extern "C" void kernel_launch(void* const* d_in, const int* in_sizes, int n_in,
                              void* d_out, int out_size)
{
    const float* x   = (const float*)d_in[0];
    const void*  ei  = d_in[1];
    const float* W1  = (const float*)d_in[2];
    const float* b1  = (const float*)d_in[3];
    const float* g1  = (const float*)d_in[4];
    const float* be1 = (const float*)d_in[5];
    const float* W2  = (const float*)d_in[6];
    const float* b2  = (const float*)d_in[7];
    const float* g2  = (const float*)d_in[8];
    const float* be2 = (const float*)d_in[9];

    int N = in_sizes[0] / DD;  if (N > NN)   N = NN;
    int E = in_sizes[1] / 2;   if (E > EMAX) E = EMAX;
    float* out = (float*)d_out;

    __half* hs;
    float* x2;
    void* degi;
    cudaGetSymbolAddress((void**)&hs,  g_hs);
    cudaGetSymbolAddress((void**)&x2,  g_x2);
    cudaGetSymbolAddress(&degi, g_degi);

    const int T = 256;
    cudaFuncSetAttribute(k_gemm, cudaFuncAttributeMaxDynamicSharedMemorySize, SM_TOTAL);

    int ebl = (E + T - 1) / T;
    int abl = (N + 7) / 8;
    int gbl = (N + 127) / 128;

    // side stream + fork/join events (host objects; created per call,
    // intentionally not destroyed -- destroying during capture is illegal,
    // and kernel_launch is only invoked a handful of times)
    cudaStream_t side;
    cudaStreamCreateWithFlags(&side, cudaStreamNonBlocking);
    cudaEvent_t evFork, evJoin;
    cudaEventCreateWithFlags(&evFork, cudaEventDisableTiming);
    cudaEventCreateWithFlags(&evJoin, cudaEventDisableTiming);

    // ---- prep head (main stream): deg count + scan (produces dinv) ----
    cudaMemsetAsync(degi, 0, (size_t)N * sizeof(int));
    k_count<<<ebl, T>>>(ei, E);
    k_scan<<<1, 1024>>>(N);

    // ---- fork: gemm1 (needs x, W1, dinv) runs parallel to fill ----
    cudaEventRecord(evFork, 0);
    cudaStreamWaitEvent(side, evFork, 0);
    k_gemm<<<gbl, T, SM_TOTAL, side>>>(x, W1, hs, N);
    cudaEventRecord(evJoin, side);

    k_fill<<<ebl, T>>>(ei, E);              // main stream, concurrent w/ gemm1
    cudaStreamWaitEvent(0, evJoin, 0);      // join before aggln1

    // ---- layer 1 tail + layer 2 (main stream) ----
    k_aggln<<<abl, T>>>(hs, b1, g1, be1, x2, N);
    k_gemm<<<gbl, T, SM_TOTAL>>>(x2, W2, hs, N);
    k_aggln<<<abl, T>>>(hs, b2, g2, be2, out, N);
}